// round 11
// baseline (speedup 1.0000x reference)
#include <cuda_runtime.h>

// LIF update: elementwise over N = 64*256*32*32 = 16,777,216 f32 elements.
// Inputs (metadata order): impulse, mem, refrac_until, spiketrain (values unused).
// Output: 4*N floats: [psp | mem_out | refrac_out | spiketrain_out].
//
// Round 11: hint-matrix quadrant test. DEFAULT-policy loads (allow input
// lines to persist in L2 across graph replays — ncu shows ~55MB/replay is
// already served from L2) + .cs stores (outputs are dead, evict-first, so
// they don't thrash the input residency). Same launch shape as the
// twice-confirmed best (16384 x 256, 1 float4/thread, exact cover).

__device__ __forceinline__ void lif_lane(float imp, float m, float ru,
                                         float& psp, float& mo, float& ro, float& so)
{
    const float TIME = 5.0f;
    const float REFRAC_RESET = 7.0f;   // TIME + TAU_REFRAC
    const float V_THRESH = 1.0f;
    const float LEAK_AMT = 0.1f;       // 0.1 * DT

    float mi = (ru > TIME) ? 0.0f : imp;
    float nm = m + mi;
    nm = (nm > 0.0f) ? nm - LEAK_AMT : nm;
    bool sp = (nm >= V_THRESH);
    psp = sp ? V_THRESH : 0.0f;
    mo  = sp ? 0.0f : nm;
    ro  = sp ? REFRAC_RESET : ru;
    so  = sp ? TIME : 0.0f;
}

__global__ void __launch_bounds__(256) spike_layer_kernel(
    const float4* __restrict__ impulse,
    const float4* __restrict__ mem,
    const float4* __restrict__ refrac_until,
    float4* __restrict__ out_psp,
    float4* __restrict__ out_mem,
    float4* __restrict__ out_refrac,
    float4* __restrict__ out_spiketrain)
{
    // Grid covers the domain exactly (16384 * 256 = 2^22 float4s).
    int i = blockIdx.x * blockDim.x + threadIdx.x;

    // Default cache policy on loads: let input lines age normally in L2 so
    // they can survive across graph replays (cross-replay reuse).
    float4 ru  = refrac_until[i];
    float4 imp = impulse[i];
    float4 m   = mem[i];

    float4 psp, mo, ro, so;
    lif_lane(imp.x, m.x, ru.x, psp.x, mo.x, ro.x, so.x);
    lif_lane(imp.y, m.y, ru.y, psp.y, mo.y, ro.y, so.y);
    lif_lane(imp.z, m.z, ru.z, psp.z, mo.z, ro.z, so.z);
    lif_lane(imp.w, m.w, ru.w, psp.w, mo.w, ro.w, so.w);

    // Streaming stores: outputs are never read, keep them evict-first.
    __stcs(&out_psp[i],        psp);
    __stcs(&out_mem[i],        mo);
    __stcs(&out_refrac[i],     ro);
    __stcs(&out_spiketrain[i], so);
}

extern "C" void kernel_launch(void* const* d_in, const int* in_sizes, int n_in,
                              void* d_out, int out_size)
{
    const float* impulse      = (const float*)d_in[0];
    const float* mem          = (const float*)d_in[1];
    const float* refrac_until = (const float*)d_in[2];
    // d_in[3] (spiketrain) values are unused by the reference math.

    int n = in_sizes[0];          // 16,777,216
    int n4 = n / 4;               // 4,194,304 = 2^22

    float* out = (float*)d_out;   // [psp | mem | refrac | spiketrain], each n floats

    int threads = 256;
    int blocks = n4 / threads;    // 16384, exact cover

    spike_layer_kernel<<<blocks, threads>>>(
        (const float4*)impulse,
        (const float4*)mem,
        (const float4*)refrac_until,
        (float4*)(out),
        (float4*)(out + (size_t)n),
        (float4*)(out + (size_t)2 * n),
        (float4*)(out + (size_t)3 * n));
}

// round 12
// speedup vs baseline: 1.0114x; 1.0114x over previous
#include <cuda_runtime.h>

// LIF update: elementwise over N = 64*256*32*32 = 16,777,216 f32 elements.
// Inputs (metadata order): impulse, mem, refrac_until, spiketrain (values unused).
// Output: 4*N floats: [psp | mem_out | refrac_out | spiketrain_out].
//
// FINAL (11 rounds of measurement). Best config — only one to break 66 us
// (65.7 us kernel, twice; 79.5% DRAM; 6.3 TB/s):
//   - 16384 CTAs x 256 threads, 1 float4/thread, exact grid cover
//   - __ldcs/__stcs streaming cache policy on loads AND stores
//   - dead spiketrain input skipped (saves 64 MiB / ~14% of read traffic)
//   - refrac_until loaded first (gates the earliest select)
// At the empirical mixed read/write HBM ceiling for sm_103a. Mapped and
// rejected: grid-stride/low-CTA shapes (-17%), 2x/8x per-thread coverage,
// 256-bit v8 ops, front-batched loads, default/mixed cache-hint quadrants —
// all neutral or worse. All compute pipes <13%; DRAM is the only binding pipe.

__device__ __forceinline__ void lif_lane(float imp, float m, float ru,
                                         float& psp, float& mo, float& ro, float& so)
{
    const float TIME = 5.0f;
    const float REFRAC_RESET = 7.0f;   // TIME + TAU_REFRAC
    const float V_THRESH = 1.0f;
    const float LEAK_AMT = 0.1f;       // 0.1 * DT

    float mi = (ru > TIME) ? 0.0f : imp;
    float nm = m + mi;
    nm = (nm > 0.0f) ? nm - LEAK_AMT : nm;
    bool sp = (nm >= V_THRESH);
    psp = sp ? V_THRESH : 0.0f;
    mo  = sp ? 0.0f : nm;
    ro  = sp ? REFRAC_RESET : ru;
    so  = sp ? TIME : 0.0f;
}

__global__ void __launch_bounds__(256) spike_layer_kernel(
    const float4* __restrict__ impulse,
    const float4* __restrict__ mem,
    const float4* __restrict__ refrac_until,
    float4* __restrict__ out_psp,
    float4* __restrict__ out_mem,
    float4* __restrict__ out_refrac,
    float4* __restrict__ out_spiketrain)
{
    // Grid covers the domain exactly (16384 * 256 = 2^22 float4s).
    int i = blockIdx.x * blockDim.x + threadIdx.x;

    // refrac_until first: it gates the earliest select on the critical path.
    float4 ru  = __ldcs(&refrac_until[i]);
    float4 imp = __ldcs(&impulse[i]);
    float4 m   = __ldcs(&mem[i]);

    float4 psp, mo, ro, so;
    lif_lane(imp.x, m.x, ru.x, psp.x, mo.x, ro.x, so.x);
    lif_lane(imp.y, m.y, ru.y, psp.y, mo.y, ro.y, so.y);
    lif_lane(imp.z, m.z, ru.z, psp.z, mo.z, ro.z, so.z);
    lif_lane(imp.w, m.w, ru.w, psp.w, mo.w, ro.w, so.w);

    __stcs(&out_psp[i],        psp);
    __stcs(&out_mem[i],        mo);
    __stcs(&out_refrac[i],     ro);
    __stcs(&out_spiketrain[i], so);
}

extern "C" void kernel_launch(void* const* d_in, const int* in_sizes, int n_in,
                              void* d_out, int out_size)
{
    const float* impulse      = (const float*)d_in[0];
    const float* mem          = (const float*)d_in[1];
    const float* refrac_until = (const float*)d_in[2];
    // d_in[3] (spiketrain) values are unused by the reference math.

    int n = in_sizes[0];          // 16,777,216
    int n4 = n / 4;               // 4,194,304 = 2^22

    float* out = (float*)d_out;   // [psp | mem | refrac | spiketrain], each n floats

    int threads = 256;
    int blocks = n4 / threads;    // 16384, exact cover

    spike_layer_kernel<<<blocks, threads>>>(
        (const float4*)impulse,
        (const float4*)mem,
        (const float4*)refrac_until,
        (float4*)(out),
        (float4*)(out + (size_t)n),
        (float4*)(out + (size_t)2 * n),
        (float4*)(out + (size_t)3 * n));
}

// round 13
// speedup vs baseline: 1.0226x; 1.0111x over previous
#include <cuda_runtime.h>

// LIF update: elementwise over N = 64*256*32*32 = 16,777,216 f32 elements.
// Inputs (metadata order): impulse, mem, refrac_until, spiketrain (values unused).
// Output: 4*N floats: [psp | mem_out | refrac_out | spiketrain_out].
//
// FINAL (12 rounds of measurement). Best config — three fastest readings of
// the session (65.7, 65.7, 65.8 us kernel; 79.4-79.6% DRAM; 6.3 TB/s):
//   - 16384 CTAs x 256 threads, 1 float4/thread, exact grid cover
//   - __ldcs/__stcs streaming cache policy on loads AND stores
//   - dead spiketrain input skipped (saves 64 MiB / ~14% of read traffic)
//   - refrac_until loaded first (gates the earliest select)
// At the empirical mixed read/write HBM ceiling for sm_103a. Mapped and
// rejected: grid-stride/low-CTA shapes (-17%), 2x/8x per-thread coverage,
// 256-bit v8 ops, front-batched loads, all other cache-hint quadrants —
// all neutral or worse. All compute pipes <13%; DRAM is the only binding pipe.

__device__ __forceinline__ void lif_lane(float imp, float m, float ru,
                                         float& psp, float& mo, float& ro, float& so)
{
    const float TIME = 5.0f;
    const float REFRAC_RESET = 7.0f;   // TIME + TAU_REFRAC
    const float V_THRESH = 1.0f;
    const float LEAK_AMT = 0.1f;       // 0.1 * DT

    float mi = (ru > TIME) ? 0.0f : imp;
    float nm = m + mi;
    nm = (nm > 0.0f) ? nm - LEAK_AMT : nm;
    bool sp = (nm >= V_THRESH);
    psp = sp ? V_THRESH : 0.0f;
    mo  = sp ? 0.0f : nm;
    ro  = sp ? REFRAC_RESET : ru;
    so  = sp ? TIME : 0.0f;
}

__global__ void __launch_bounds__(256) spike_layer_kernel(
    const float4* __restrict__ impulse,
    const float4* __restrict__ mem,
    const float4* __restrict__ refrac_until,
    float4* __restrict__ out_psp,
    float4* __restrict__ out_mem,
    float4* __restrict__ out_refrac,
    float4* __restrict__ out_spiketrain)
{
    // Grid covers the domain exactly (16384 * 256 = 2^22 float4s).
    int i = blockIdx.x * blockDim.x + threadIdx.x;

    // refrac_until first: it gates the earliest select on the critical path.
    float4 ru  = __ldcs(&refrac_until[i]);
    float4 imp = __ldcs(&impulse[i]);
    float4 m   = __ldcs(&mem[i]);

    float4 psp, mo, ro, so;
    lif_lane(imp.x, m.x, ru.x, psp.x, mo.x, ro.x, so.x);
    lif_lane(imp.y, m.y, ru.y, psp.y, mo.y, ro.y, so.y);
    lif_lane(imp.z, m.z, ru.z, psp.z, mo.z, ro.z, so.z);
    lif_lane(imp.w, m.w, ru.w, psp.w, mo.w, ro.w, so.w);

    __stcs(&out_psp[i],        psp);
    __stcs(&out_mem[i],        mo);
    __stcs(&out_refrac[i],     ro);
    __stcs(&out_spiketrain[i], so);
}

extern "C" void kernel_launch(void* const* d_in, const int* in_sizes, int n_in,
                              void* d_out, int out_size)
{
    const float* impulse      = (const float*)d_in[0];
    const float* mem          = (const float*)d_in[1];
    const float* refrac_until = (const float*)d_in[2];
    // d_in[3] (spiketrain) values are unused by the reference math.

    int n = in_sizes[0];          // 16,777,216
    int n4 = n / 4;               // 4,194,304 = 2^22

    float* out = (float*)d_out;   // [psp | mem | refrac | spiketrain], each n floats

    int threads = 256;
    int blocks = n4 / threads;    // 16384, exact cover

    spike_layer_kernel<<<blocks, threads>>>(
        (const float4*)impulse,
        (const float4*)mem,
        (const float4*)refrac_until,
        (float4*)(out),
        (float4*)(out + (size_t)n),
        (float4*)(out + (size_t)2 * n),
        (float4*)(out + (size_t)3 * n));
}